// round 6
// baseline (speedup 1.0000x reference)
#include <cuda_runtime.h>
#include <cstddef>

#define EDIM 1024
#define BLK  256
#define FPB  4            // features per block in compute_y
#define YGRID (EDIM / FPB) // 256 blocks

__device__ float g_y[EDIM];   // y = W @ z + b

// ---------------------------------------------------------------------------
// Fused prologue: 256 blocks x 256 threads. Each block:
//   1) issues its W prefetch (4 rows x 4 KB, evict-first) -- in flight while...
//   2) ...computing z[0..1023] into smem with fast trig (once per block;
//      aggregate MUFU cost across 256 blocks ~0.4us),
//   3) dots 4 W rows with z -> g_y[f].
// Small block count leaves the SMs free for broadcast to pre-ramp under PDL.
// ---------------------------------------------------------------------------
__global__ void __launch_bounds__(BLK)
compute_y_kernel(const float* __restrict__ bs_theta,
                 const float* __restrict__ bs_phi,
                 const float* __restrict__ phases,
                 const float* __restrict__ squeeze_r,
                 const float* __restrict__ disp_r,
                 const float* __restrict__ W,
                 const float* __restrict__ bvec) {
    __shared__ float zsh[EDIM];
    __shared__ float red2[2 * FPB];

    const int tid = threadIdx.x;
    const int f0  = blockIdx.x * FPB;
    const int j   = tid >> 6;         // feature slot 0..3 (64 threads each)
    const int k   = tid & 63;         // index within feature group

    // ---- 1) Prefetch W rows first (var-lat loads overlap the trig below).
    const float4* __restrict__ wrow =
        reinterpret_cast<const float4*>(W + (size_t)(f0 + j) * EDIM);
    float4 w0 = __ldcs(&wrow[k]);
    float4 w1 = __ldcs(&wrow[k + 64]);
    float4 w2 = __ldcs(&wrow[k + 128]);
    float4 w3 = __ldcs(&wrow[k + 192]);
    float bias = (k == 0) ? bvec[f0 + j] : 0.f;

    // ---- 2) Compute z into shared memory (4 wires per thread).
    float c0, s0, c1, s1;
    __sincosf(0.5f * bs_theta[0], &s0, &c0);
    __sincosf(0.5f * bs_phi[0],   &s1, &c1);

    #pragma unroll
    for (int kk = 0; kk < EDIM / BLK; kk++) {
        const int e = tid + BLK * kk;

        float ar = 1.f, ai = 0.f, br = 0.f, bi = 0.f;
        // rx(bs_theta)
        {
            float nar =  c0 * ar + s0 * bi;
            float nai =  c0 * ai - s0 * br;
            float nbr =  s0 * ai + c0 * br;
            float nbi = -s0 * ar + c0 * bi;
            ar = nar; ai = nai; br = nbr; bi = nbi;
        }
        // ry(bs_phi)
        {
            float nar = c1 * ar - s1 * br;
            float nai = c1 * ai - s1 * bi;
            float nbr = s1 * ar + c1 * br;
            float nbi = s1 * ai + c1 * bi;
            ar = nar; ai = nai; br = nbr; bi = nbi;
        }
        // rz(phases[e])
        {
            float cp, sp;
            __sincosf(0.5f * phases[e], &sp, &cp);
            float nar = cp * ar + sp * ai;
            float nai = cp * ai - sp * ar;
            float nbr = cp * br - sp * bi;
            float nbi = cp * bi + sp * br;
            ar = nar; ai = nai; br = nbr; bi = nbi;
        }
        // ry(squeeze_r[e])
        {
            float c, s;
            __sincosf(0.5f * squeeze_r[e], &s, &c);
            float nar = c * ar - s * br;
            float nai = c * ai - s * bi;
            float nbr = s * ar + c * br;
            float nbi = s * ai + c * bi;
            ar = nar; ai = nai; br = nbr; bi = nbi;
        }
        // rx(displacement_r[e])
        {
            float c, s;
            __sincosf(0.5f * disp_r[e], &s, &c);
            float nar =  c * ar + s * bi;
            float nai =  c * ai - s * br;
            float nbr =  s * ai + c * br;
            float nbi = -s * ar + c * bi;
            ar = nar; ai = nai; br = nbr; bi = nbi;
        }
        // rz(kerr) rotates phases only -> |amp|^2 unchanged. Dropped.

        zsh[e] = (ar * ar + ai * ai) - (br * br + bi * bi);
    }
    __syncthreads();

    // ---- 3) Dot: feature j, 64 threads, 4 float4s each.
    const float4* __restrict__ z4 = reinterpret_cast<const float4*>(zsh);
    float4 za = z4[k], zb = z4[k + 64], zc = z4[k + 128], zd = z4[k + 192];
    float p = w0.x * za.x + w0.y * za.y + w0.z * za.z + w0.w * za.w
            + w1.x * zb.x + w1.y * zb.y + w1.z * zb.z + w1.w * zb.w
            + w2.x * zc.x + w2.y * zc.y + w2.z * zc.z + w2.w * zc.w
            + w3.x * zd.x + w3.y * zd.y + w3.z * zd.z + w3.w * zd.w;

    #pragma unroll
    for (int o = 16; o > 0; o >>= 1)
        p += __shfl_down_sync(0xffffffffu, p, o);

    // two warps per feature -> combine via smem
    if ((tid & 31) == 0) red2[tid >> 5] = p;   // slots 0..7 = (feature, half)
    __syncthreads();
    if (k == 0)
        g_y[f0 + j] = red2[2 * j] + red2[2 * j + 1] + bias;

    __threadfence();
    cudaTriggerProgrammaticLaunchCompletion();
}

// ---------------------------------------------------------------------------
// Broadcast y over (B, S). PDL-dependent: blocks pre-ramp under compute_y,
// sync, load their float4 of y (EDIM/4 == BLK), then pure STG.128 stream.
// DRAM-write-bound floor ~41us at ~5TB/s.
// ---------------------------------------------------------------------------
__global__ void __launch_bounds__(BLK)
broadcast_kernel(float4* __restrict__ out, size_t n4) {
    const int tid = threadIdx.x;
    const size_t stride = (size_t)gridDim.x * BLK;
    size_t i = (size_t)blockIdx.x * BLK + tid;

    cudaGridDependencySynchronize();
    const float4 v = *reinterpret_cast<const float4*>(&g_y[tid * 4]);

    for (; i + 7 * stride < n4; i += 8 * stride) {
        __stcs(out + i,              v);
        __stcs(out + i + stride,     v);
        __stcs(out + i + 2 * stride, v);
        __stcs(out + i + 3 * stride, v);
        __stcs(out + i + 4 * stride, v);
        __stcs(out + i + 5 * stride, v);
        __stcs(out + i + 6 * stride, v);
        __stcs(out + i + 7 * stride, v);
    }
    for (; i < n4; i += stride)
        __stcs(out + i, v);
}

// ---------------------------------------------------------------------------
// Inputs (metadata order):
//   0: x (B,S,E) f32        -- UNUSED (output is x-independent)
//   1: bs_theta (1,) f32
//   2: bs_phi   (1,) f32
//   3: phases   (E,) f32
//   4: squeeze_r(E,) f32
//   5: displacement_r (E,) f32
//   6: kerr     (E,) f32    -- UNUSED (rz does not change |amp|^2)
//   7: W_combine (E,E) f32
//   8: b_combine (E,) f32
// Output: (B,S,E) f32
// ---------------------------------------------------------------------------
extern "C" void kernel_launch(void* const* d_in, const int* in_sizes, int n_in,
                              void* d_out, int out_size) {
    const float* bs_theta = (const float*)d_in[1];
    const float* bs_phi   = (const float*)d_in[2];
    const float* phases   = (const float*)d_in[3];
    const float* squeeze  = (const float*)d_in[4];
    const float* disp     = (const float*)d_in[5];
    const float* W        = (const float*)d_in[7];
    const float* bvec     = (const float*)d_in[8];

    // Node 1: fused prologue (small grid -> leaves room for broadcast ramp).
    compute_y_kernel<<<YGRID, BLK>>>(bs_theta, bs_phi, phases, squeeze, disp,
                                     W, bvec);

    // Node 2: PDL launch — pre-ramps under the prologue.
    const size_t n4 = (size_t)out_size / 4;   // 16,777,216 float4s
    {
        cudaLaunchConfig_t cfg = {};
        cfg.gridDim  = dim3(2048);
        cfg.blockDim = dim3(BLK);
        cfg.stream   = 0;
        cudaLaunchAttribute attr[1];
        attr[0].id = cudaLaunchAttributeProgrammaticStreamSerialization;
        attr[0].val.programmaticStreamSerializationAllowed = 1;
        cfg.attrs = attr;
        cfg.numAttrs = 1;
        cudaLaunchKernelEx(&cfg, broadcast_kernel, (float4*)d_out, n4);
    }
}